// round 14
// baseline (speedup 1.0000x reference)
#include <cuda_runtime.h>
#include <cuda_fp16.h>
#include <cstdint>
#include <cstddef>

#define NN 100000
#define NE 1600000
#define DD 128
#define NPAD 100096          // 782 * 128
#define NTILE 782
#define NB_SCAN 98           // ceil(100000 / 1024)

// combo kernel grid sections
#define CB_CONV  12500       // convert_x blocks
#define CB_ZERO  98          // zero cnt blocks
#define CB_PREP  32          // prep_w blocks
#define CB_TOTAL (CB_CONV + CB_ZERO + CB_PREP + 1)  // +1 detect

// ---------------------------------------------------------------------------
// Device scratch (no allocation allowed)
// ---------------------------------------------------------------------------
__device__ __align__(16) __half g_xf[(size_t)NPAD * DD];    // x as fp16
__device__ __align__(16) __half g_hf[(size_t)NPAD * DD];    // h as fp16
__device__ __align__(16) __half g_wpack[4 * 128 * 128];     // Wl1,Wr1,Wl2,Wr2 fp16
__device__ int g_srcs[NE];
__device__ int g_rp[NN + 1];
__device__ int g_pos[NN];
__device__ int g_cnt[NN];
__device__ int g_bs[128];
__device__ int g_is64;

// ---------------------------------------------------------------------------
// helpers
// ---------------------------------------------------------------------------
__device__ __forceinline__ uint32_t smem_to_u32(const void* p) {
    uint32_t a;
    asm("{ .reg .u64 t; cvta.to.shared.u64 t, %1; cvt.u32.u64 %0, t; }"
        : "=r"(a) : "l"(p));
    return a;
}
__device__ __forceinline__ void cp_async16(uint32_t saddr, const void* gptr) {
    asm volatile("cp.async.cg.shared.global [%0], [%1], 16;"
                 :: "r"(saddr), "l"(gptr));
}
#define CP_COMMIT() asm volatile("cp.async.commit_group;" ::: "memory")
#define CP_WAIT0()  asm volatile("cp.async.wait_group 0;" ::: "memory")

// ---------------------------------------------------------------------------
// Combo kernel: [convert_x | zero cnt | prep_w | detect] by grid section.
// ---------------------------------------------------------------------------
__global__ void combo_kernel(const float4* __restrict__ x,
                             const unsigned int* __restrict__ ebuf,
                             const float* __restrict__ Wl1, const float* __restrict__ Wr1,
                             const float* __restrict__ Wl2, const float* __restrict__ Wr2,
                             __half* __restrict__ xf,
                             __half* __restrict__ wpack,
                             int* __restrict__ cnt) {
    const int b = blockIdx.x;
    const int t = threadIdx.x;

    if (b < CB_CONV) {
        const int id = b * 256 + t;
        const int row = id >> 5, lane = id & 31;
        if (row >= NN) return;
        float4 v = x[(size_t)row * 32 + lane];
        __half2 f0 = __floats2half2_rn(v.x, v.y);
        __half2 f1 = __floats2half2_rn(v.z, v.w);
        *(uint2*)(xf + (size_t)row * DD + lane * 4) =
            make_uint2(*(unsigned*)&f0, *(unsigned*)&f1);
    } else if (b < CB_CONV + CB_ZERO) {
        const int i = (b - CB_CONV) * 256 + t;
        if (i < NN / 4) ((int4*)cnt)[i] = make_int4(0, 0, 0, 0);
    } else if (b < CB_CONV + CB_ZERO + CB_PREP) {
        const int id = (b - CB_CONV - CB_ZERO) * 256 + t;   // 0..8191
        const int tIdx = id >> 11;
        const int rem = id & 2047;
        const int j = rem >> 4, cu = rem & 15;
        const float* W = (tIdx == 0) ? Wl1 : (tIdx == 1) ? Wr1 : (tIdx == 2) ? Wl2 : Wr2;
        const float4* p = (const float4*)(W + (size_t)j * DD + cu * 8);
        float4 v0 = p[0], v1 = p[1];
        __half2 h0 = __floats2half2_rn(v0.x, v0.y);
        __half2 h1 = __floats2half2_rn(v0.z, v0.w);
        __half2 h2 = __floats2half2_rn(v1.x, v1.y);
        __half2 h3 = __floats2half2_rn(v1.z, v1.w);
        __half* dst = wpack + (size_t)tIdx * 16384 + (size_t)j * DD + cu * 8;
        *(uint4*)dst = make_uint4(*(unsigned*)&h0, *(unsigned*)&h1,
                                  *(unsigned*)&h2, *(unsigned*)&h3);
    } else {
        __shared__ int nz;
        if (t == 0) nz = 0;
        __syncthreads();
        for (int i = t; i < 8192; i += 256)
            if (ebuf[2 * i + 1] != 0u) nz = 1;
        __syncthreads();
        if (t == 0) g_is64 = (nz == 0) ? 1 : 0;
    }
}

// ---------------------------------------------------------------------------
// hist: 2 edges per thread via 16B loads
// ---------------------------------------------------------------------------
__global__ void hist_kernel(const void* __restrict__ edges, int* __restrict__ cnt) {
    const int is64 = g_is64;
    int i2 = blockIdx.x * blockDim.x + threadIdx.x;
    const int stride = gridDim.x * blockDim.x;
    if (is64) {
        const longlong2* d = (const longlong2*)((const long long*)edges + NE);
        for (; i2 < NE / 2; i2 += stride) {
            longlong2 v = __ldg(&d[i2]);
            atomicAdd(&cnt[(int)v.x], 1);
            atomicAdd(&cnt[(int)v.y], 1);
        }
    } else {
        const int2* d = (const int2*)((const int*)edges + NE);
        for (; i2 < NE / 2; i2 += stride) {
            int2 v = __ldg(&d[i2]);
            atomicAdd(&cnt[v.x], 1);
            atomicAdd(&cnt[v.y], 1);
        }
    }
}

// ---------------------------------------------------------------------------
// scan1: per-1024-block exclusive scan, emits block sums
// ---------------------------------------------------------------------------
__global__ void scan1_kernel(const int* __restrict__ cnt, int* __restrict__ rp,
                             int* __restrict__ bs) {
    __shared__ int wsum[8];
    const int t = threadIdx.x, lane = t & 31, w = t >> 5;
    const int base = blockIdx.x * 1024 + t * 4;
    int v0 = (base + 0 < NN) ? cnt[base + 0] : 0;
    int v1 = (base + 1 < NN) ? cnt[base + 1] : 0;
    int v2 = (base + 2 < NN) ? cnt[base + 2] : 0;
    int v3 = (base + 3 < NN) ? cnt[base + 3] : 0;
    const int tot = v0 + v1 + v2 + v3;
    int inc = tot;
#pragma unroll
    for (int off = 1; off < 32; off <<= 1) {
        int n = __shfl_up_sync(0xffffffff, inc, off);
        if (lane >= off) inc += n;
    }
    if (lane == 31) wsum[w] = inc;
    __syncthreads();
    if (w == 0) {
        int s = (lane < 8) ? wsum[lane] : 0;
#pragma unroll
        for (int off = 1; off < 8; off <<= 1) {
            int n = __shfl_up_sync(0xffffffff, s, off);
            if (lane >= off) s += n;
        }
        if (lane < 8) wsum[lane] = s;
    }
    __syncthreads();
    const int wbase = (w > 0) ? wsum[w - 1] : 0;
    const int exc = wbase + inc - tot;
    if (base + 0 < NN) rp[base + 0] = exc;
    if (base + 1 < NN) rp[base + 1] = exc + v0;
    if (base + 2 < NN) rp[base + 2] = exc + v0 + v1;
    if (base + 3 < NN) rp[base + 3] = exc + v0 + v1 + v2;
    if (t == 255) bs[blockIdx.x] = wbase + inc;
}

// ---------------------------------------------------------------------------
// scan23: each block redundantly scans the 98 block sums, then applies.
// ---------------------------------------------------------------------------
__global__ void scan23_kernel(int* __restrict__ rp, int* __restrict__ pos,
                              const int* __restrict__ bs) {
    __shared__ int sbs[NB_SCAN];
    const int t = threadIdx.x;
    if (t < NB_SCAN) sbs[t] = bs[t];
    __syncthreads();
    const int i = blockIdx.x * blockDim.x + t;
    if (i < NN) {
        const int k = i >> 10;
        int pre = 0;
        for (int j = 0; j < k; ++j) pre += sbs[j];
        const int v = rp[i] + pre;
        rp[i] = v;
        pos[i] = v;
    }
    if (i == 0) rp[NN] = NE;
}

// ---------------------------------------------------------------------------
// fill: 2 edges per thread via 16B loads
// ---------------------------------------------------------------------------
__global__ void fill_kernel(const void* __restrict__ edges, int* __restrict__ pos,
                            int* __restrict__ srcs) {
    const int is64 = g_is64;
    int i2 = blockIdx.x * blockDim.x + threadIdx.x;
    const int stride = gridDim.x * blockDim.x;
    if (is64) {
        const longlong2* sp = (const longlong2*)edges;
        const longlong2* dp = (const longlong2*)((const long long*)edges + NE);
        for (; i2 < NE / 2; i2 += stride) {
            longlong2 s = __ldg(&sp[i2]);
            longlong2 d = __ldg(&dp[i2]);
            srcs[atomicAdd(&pos[(int)d.x], 1)] = (int)s.x;
            srcs[atomicAdd(&pos[(int)d.y], 1)] = (int)s.y;
        }
    } else {
        const int2* sp = (const int2*)edges;
        const int2* dp = (const int2*)((const int*)edges + NE);
        for (; i2 < NE / 2; i2 += stride) {
            int2 s = __ldg(&sp[i2]);
            int2 d = __ldg(&dp[i2]);
            srcs[atomicAdd(&pos[d.x], 1)] = s.x;
            srcs[atomicAdd(&pos[d.y], 1)] = s.y;
        }
    }
}

// ---------------------------------------------------------------------------
// Fused layer kernel: gather (into SMEM) + fp16 MMA GEMM + epilogue.
//   out = mean_agg @ Wl^T + bias + x @ Wr^T   [+ relu]
// CTA = 128 rows. SMEM slots (each 128 x 144B = 18432B):
//   0: agg k0   1: agg k64   2: x k0   3: x k64   4: B buf0   5: B buf1
// Phase A: cp.async x chunks + Wr chunks; gather agg to smem; wait; sync.
// Phase B: MMA x.Wr (2 chunks); sync; cp.async Wl chunks; wait; sync;
//          MMA agg.Wl (2 chunks); epilogue.
// ---------------------------------------------------------------------------
#define PADB 144
#define BUF  (128 * PADB)           // 18432
#define FUSED_SMEM (6 * BUF)        // 110592

struct MmaGeo { int a_row, a_kb, b_row, b_kb; };

__device__ __forceinline__ void mma_chunk(float (&acc)[4][4][4],
                                          uint32_t uA, uint32_t uB,
                                          const MmaGeo& g) {
#pragma unroll
    for (int ks = 0; ks < 4; ++ks) {
        uint32_t af[4][4];
#pragma unroll
        for (int mt = 0; mt < 4; ++mt) {
            const uint32_t addr = uA + (g.a_row + mt * 16) * PADB + ks * 32 + g.a_kb;
            asm volatile("ldmatrix.sync.aligned.m8n8.x4.shared.b16 {%0,%1,%2,%3}, [%4];"
                         : "=r"(af[mt][0]), "=r"(af[mt][1]),
                           "=r"(af[mt][2]), "=r"(af[mt][3])
                         : "r"(addr));
        }
        uint32_t bfr[4][2];
#pragma unroll
        for (int nt = 0; nt < 4; ++nt) {
            const uint32_t addr = uB + (g.b_row + nt * 8) * PADB + ks * 32 + g.b_kb;
            asm volatile("ldmatrix.sync.aligned.m8n8.x2.shared.b16 {%0,%1}, [%2];"
                         : "=r"(bfr[nt][0]), "=r"(bfr[nt][1])
                         : "r"(addr));
        }
#pragma unroll
        for (int mt = 0; mt < 4; ++mt)
#pragma unroll
            for (int nt = 0; nt < 4; ++nt) {
                asm volatile(
                    "mma.sync.aligned.m16n8k16.row.col.f32.f16.f16.f32 "
                    "{%0,%1,%2,%3}, {%4,%5,%6,%7}, {%8,%9}, {%0,%1,%2,%3};"
                    : "+f"(acc[mt][nt][0]), "+f"(acc[mt][nt][1]),
                      "+f"(acc[mt][nt][2]), "+f"(acc[mt][nt][3])
                    : "r"(af[mt][0]), "r"(af[mt][1]),
                      "r"(af[mt][2]), "r"(af[mt][3]),
                      "r"(bfr[nt][0]), "r"(bfr[nt][1]));
            }
    }
}

__global__ void __launch_bounds__(256, 2)
fused_layer_kernel(const __half* __restrict__ xin,   // features: x (L1) or h (L2)
                   const int* __restrict__ rp,
                   const int* __restrict__ srcs,
                   const __half* __restrict__ w,     // +0 Wl, +16384 Wr
                   const float* __restrict__ bias,
                   float* __restrict__ outf,
                   __half* __restrict__ of16,
                   int relu_split)
{
    extern __shared__ char smem[];
    const uint32_t uS = smem_to_u32(smem);

    const int tid  = threadIdx.x;
    const int wid  = tid >> 5;
    const int lane = tid & 31;
    const int wm   = wid >> 2;
    const int wn   = wid & 3;
    const int row0 = blockIdx.x << 7;

    // ---- Phase A1: async loads of x chunks (slots 2,3) and Wr chunks (4,5) ----
    {
        const __half* As = xin + (size_t)row0 * DD;
        const __half* Wr = w + 16384;
#pragma unroll
        for (int i = 0; i < 4; ++i) {
            const int u = i * 256 + tid;
            const int r = u >> 3, g = u & 7;
            cp_async16(uS + 2 * BUF + r * PADB + g * 16, As + (size_t)r * DD + g * 8);
            cp_async16(uS + 3 * BUF + r * PADB + g * 16, As + (size_t)r * DD + 64 + g * 8);
            cp_async16(uS + 4 * BUF + r * PADB + g * 16, Wr + (size_t)r * DD + g * 8);
            cp_async16(uS + 5 * BUF + r * PADB + g * 16, Wr + (size_t)r * DD + 64 + g * 8);
        }
        CP_COMMIT();
    }

    // ---- Phase A2: gather this CTA's 128 rows into smem agg (warp per row) ----
    {
        const int ch = lane >> 4;                          // 0: cols 0-63, 1: 64-127
        const uint32_t sbase = uS + ch * BUF + (lane & 15) * 8;
#pragma unroll 1
        for (int j = 0; j < 16; ++j) {
            const int lrow = wid * 16 + j;
            const int row = row0 + lrow;
            float4 acc = make_float4(0.f, 0.f, 0.f, 0.f);
            int deg = 0;
            if (row < NN) {
                const int s = rp[row], e = rp[row + 1];
                deg = e - s;
                const int myidx = (s + lane < e) ? srcs[s + lane] : 0;
                const int n = (deg < 32) ? deg : 32;
#pragma unroll 4
                for (int i = 0; i < n; ++i) {
                    const int sidx = __shfl_sync(0xffffffff, myidx, i);
                    const uint2 u = __ldg((const uint2*)(xin + (size_t)sidx * DD + lane * 4));
                    float2 a0 = __half22float2(*(const __half2*)&u.x);
                    float2 a1 = __half22float2(*(const __half2*)&u.y);
                    acc.x += a0.x; acc.y += a0.y; acc.z += a1.x; acc.w += a1.y;
                }
                for (int i = s + 32; i < e; ++i) {
                    const uint2 u = __ldg((const uint2*)(xin + (size_t)srcs[i] * DD + lane * 4));
                    float2 a0 = __half22float2(*(const __half2*)&u.x);
                    float2 a1 = __half22float2(*(const __half2*)&u.y);
                    acc.x += a0.x; acc.y += a0.y; acc.z += a1.x; acc.w += a1.y;
                }
            }
            const float inv = 1.0f / fmaxf((float)deg, 1.0f);
            __half2 o0 = __floats2half2_rn(acc.x * inv, acc.y * inv);
            __half2 o1 = __floats2half2_rn(acc.z * inv, acc.w * inv);
            asm volatile("st.shared.v2.b32 [%0], {%1, %2};"
                         :: "r"(sbase + lrow * PADB), "r"(*(unsigned*)&o0),
                            "r"(*(unsigned*)&o1) : "memory");
        }
    }

    CP_WAIT0();
    __syncthreads();

    const MmaGeo geo = { wm * 64 + (lane & 15), ((lane >> 4) & 1) << 4,
                         wn * 32 + (lane & 7),  ((lane >> 3) & 1) << 4 };

    float acc[4][4][4];
#pragma unroll
    for (int mt = 0; mt < 4; ++mt)
#pragma unroll
        for (int nt = 0; nt < 4; ++nt)
#pragma unroll
            for (int q = 0; q < 4; ++q) acc[mt][nt][q] = 0.f;

    // ---- Phase B1: x @ Wr^T (chunks k0, k64) ----
    mma_chunk(acc, uS + 2 * BUF, uS + 4 * BUF, geo);
    mma_chunk(acc, uS + 3 * BUF, uS + 5 * BUF, geo);

    // ---- Phase B2: swap B buffers to Wl ----
    __syncthreads();
    {
#pragma unroll
        for (int i = 0; i < 4; ++i) {
            const int u = i * 256 + tid;
            const int r = u >> 3, g = u & 7;
            cp_async16(uS + 4 * BUF + r * PADB + g * 16, w + (size_t)r * DD + g * 8);
            cp_async16(uS + 5 * BUF + r * PADB + g * 16, w + (size_t)r * DD + 64 + g * 8);
        }
        CP_COMMIT();
        CP_WAIT0();
    }
    __syncthreads();

    // ---- Phase B3: agg @ Wl^T (chunks k0, k64) ----
    mma_chunk(acc, uS + 0 * BUF, uS + 4 * BUF, geo);
    mma_chunk(acc, uS + 1 * BUF, uS + 5 * BUF, geo);

    // ---- epilogue ----
    const int col_base = wn * 32 + ((lane & 3) << 1);
    float bv[4][2];
#pragma unroll
    for (int nt = 0; nt < 4; ++nt) {
        bv[nt][0] = __ldg(bias + col_base + nt * 8);
        bv[nt][1] = __ldg(bias + col_base + nt * 8 + 1);
    }

#pragma unroll
    for (int mt = 0; mt < 4; ++mt) {
        const int r0 = row0 + wm * 64 + mt * 16 + (lane >> 2);
        const int r1 = r0 + 8;
#pragma unroll
        for (int nt = 0; nt < 4; ++nt) {
            const int col = col_base + nt * 8;
            float v0 = acc[mt][nt][0] + bv[nt][0];
            float v1 = acc[mt][nt][1] + bv[nt][1];
            float v2 = acc[mt][nt][2] + bv[nt][0];
            float v3 = acc[mt][nt][3] + bv[nt][1];
            if (relu_split) {
                v0 = fmaxf(v0, 0.f); v1 = fmaxf(v1, 0.f);
                v2 = fmaxf(v2, 0.f); v3 = fmaxf(v3, 0.f);
                if (r0 < NN)
                    *(__half2*)(of16 + (size_t)r0 * DD + col) = __floats2half2_rn(v0, v1);
                if (r1 < NN)
                    *(__half2*)(of16 + (size_t)r1 * DD + col) = __floats2half2_rn(v2, v3);
            } else {
                if (r0 < NN) *(float2*)(outf + (size_t)r0 * DD + col) = make_float2(v0, v1);
                if (r1 < NN) *(float2*)(outf + (size_t)r1 * DD + col) = make_float2(v2, v3);
            }
        }
    }
}

// ---------------------------------------------------------------------------
// Launch sequence (default stream, graph-capturable, allocation-free)
// 7 kernels total.
// ---------------------------------------------------------------------------
extern "C" void kernel_launch(void* const* d_in, const int* in_sizes, int n_in,
                              void* d_out, int out_size)
{
    const float* x   = (const float*)d_in[0];
    const void*  ei  = d_in[1];
    const float* W1l = (const float*)d_in[2];
    const float* b1  = (const float*)d_in[3];
    const float* W1r = (const float*)d_in[4];
    const float* W2l = (const float*)d_in[5];
    const float* b2  = (const float*)d_in[6];
    const float* W2r = (const float*)d_in[7];
    float* out = (float*)d_out;

    __half *xf, *hf, *wpack;
    int *srcs, *rp, *pos, *cnt, *bs;
    cudaGetSymbolAddress((void**)&xf,    g_xf);
    cudaGetSymbolAddress((void**)&hf,    g_hf);
    cudaGetSymbolAddress((void**)&wpack, g_wpack);
    cudaGetSymbolAddress((void**)&srcs,  g_srcs);
    cudaGetSymbolAddress((void**)&rp,    g_rp);
    cudaGetSymbolAddress((void**)&pos,   g_pos);
    cudaGetSymbolAddress((void**)&cnt,   g_cnt);
    cudaGetSymbolAddress((void**)&bs,    g_bs);

    cudaFuncSetAttribute(fused_layer_kernel,
                         cudaFuncAttributeMaxDynamicSharedMemorySize, FUSED_SMEM);

    // combo: convert_x | zero cnt | prep_w | detect
    combo_kernel<<<CB_TOTAL, 256>>>((const float4*)x, (const unsigned int*)ei,
                                    W1l, W1r, W2l, W2r, xf, wpack, cnt);

    // CSR build
    hist_kernel<<<1600, 256>>>(ei, cnt);
    scan1_kernel<<<NB_SCAN, 256>>>(cnt, rp, bs);
    scan23_kernel<<<(NN + 255) / 256, 256>>>(rp, pos, bs);
    fill_kernel<<<1600, 256>>>(ei, pos, srcs);

    // Layer 1 (fused gather + GEMM)
    fused_layer_kernel<<<NTILE, 256, FUSED_SMEM>>>(xf, rp, srcs, wpack, b1,
                                                   nullptr, hf, 1);

    // Layer 2
    fused_layer_kernel<<<NTILE, 256, FUSED_SMEM>>>(hf, rp, srcs, wpack + 2 * 16384, b2,
                                                   out, nullptr, 0);
}

// round 15
// speedup vs baseline: 1.7550x; 1.7550x over previous
#include <cuda_runtime.h>
#include <cuda_fp16.h>
#include <cstdint>
#include <cstddef>

#define NN 100000
#define NE 1600000
#define DD 128
#define NPAD 100096          // 782 * 128
#define NTILE 782
#define NB_SCAN 98           // ceil(100000 / 1024)

// combo kernel grid sections: [hist | convert_x | prep_w | detect]
#define CB_HIST  1600
#define CB_CONV  12500
#define CB_PREP  32
#define CB_TOTAL (CB_HIST + CB_CONV + CB_PREP + 1)

// ---------------------------------------------------------------------------
// Device scratch (no allocation allowed)
// ---------------------------------------------------------------------------
__device__ __align__(16) __half g_xf[(size_t)NPAD * DD];    // x as fp16
__device__ __align__(16) __half g_hf[(size_t)NPAD * DD];    // h as fp16
__device__ __align__(16) __half g_aggf[(size_t)NPAD * DD];  // aggregated mean fp16
__device__ __align__(16) __half g_wpack[4 * 128 * 128];     // Wl1,Wr1,Wl2,Wr2 fp16
__device__ int g_srcs[NE];
__device__ int g_rp[NN + 1];
__device__ int g_pos[NN];
__device__ int g_cnt[NN];   // INVARIANT: all-zero at kernel_launch entry
                            // (zero-init at load; re-zeroed by scan23 each call)
__device__ int g_bs[128];
__device__ int g_is64;

// ---------------------------------------------------------------------------
// helpers
// ---------------------------------------------------------------------------
__device__ __forceinline__ uint32_t smem_to_u32(const void* p) {
    uint32_t a;
    asm("{ .reg .u64 t; cvta.to.shared.u64 t, %1; cvt.u32.u64 %0, t; }"
        : "=r"(a) : "l"(p));
    return a;
}
__device__ __forceinline__ void cp_async16(uint32_t saddr, const void* gptr) {
    asm volatile("cp.async.cg.shared.global [%0], [%1], 16;"
                 :: "r"(saddr), "l"(gptr));
}
#define CP_COMMIT() asm volatile("cp.async.commit_group;" ::: "memory")
#define CP_WAIT1()  asm volatile("cp.async.wait_group 1;" ::: "memory")
#define CP_WAIT0()  asm volatile("cp.async.wait_group 0;" ::: "memory")

// ---------------------------------------------------------------------------
// Combo kernel: [hist | convert_x | prep_w | detect] by grid section.
// hist uses a per-block local dtype detect (256 odd-word samples) so it does
// not depend on the global detect block. cnt is already zero on entry
// (invariant maintained by scan23 of the PREVIOUS call + load-time init).
// ---------------------------------------------------------------------------
__global__ void combo_kernel(const float4* __restrict__ x,
                             const unsigned int* __restrict__ ebuf,
                             const float* __restrict__ Wl1, const float* __restrict__ Wr1,
                             const float* __restrict__ Wl2, const float* __restrict__ Wr2,
                             __half* __restrict__ xf,
                             __half* __restrict__ wpack,
                             int* __restrict__ cnt) {
    const int b = blockIdx.x;
    const int t = threadIdx.x;

    if (b < CB_HIST) {
        // ---- histogram of dst degrees (local dtype detect) ----
        __shared__ int nz;
        if (t == 0) nz = 0;
        __syncthreads();
        if (ebuf[2 * t + 1] != 0u) nz = 1;   // 256 samples: int64 => all zero
        __syncthreads();
        const int is64 = (nz == 0);
        int i2 = b * 256 + t;
        const int stride = CB_HIST * 256;
        if (is64) {
            const longlong2* d = (const longlong2*)((const long long*)ebuf + NE);
            for (; i2 < NE / 2; i2 += stride) {
                longlong2 v = __ldg(&d[i2]);
                atomicAdd(&cnt[(int)v.x], 1);
                atomicAdd(&cnt[(int)v.y], 1);
            }
        } else {
            const int2* d = (const int2*)((const int*)ebuf + NE);
            for (; i2 < NE / 2; i2 += stride) {
                int2 v = __ldg(&d[i2]);
                atomicAdd(&cnt[v.x], 1);
                atomicAdd(&cnt[v.y], 1);
            }
        }
    } else if (b < CB_HIST + CB_CONV) {
        // ---- convert x -> fp16 ----
        const int id = (b - CB_HIST) * 256 + t;
        const int row = id >> 5, lane = id & 31;
        if (row >= NN) return;
        float4 v = x[(size_t)row * 32 + lane];
        __half2 f0 = __floats2half2_rn(v.x, v.y);
        __half2 f1 = __floats2half2_rn(v.z, v.w);
        *(uint2*)(xf + (size_t)row * DD + lane * 4) =
            make_uint2(*(unsigned*)&f0, *(unsigned*)&f1);
    } else if (b < CB_HIST + CB_CONV + CB_PREP) {
        // ---- weight pack fp32 -> fp16 ----
        const int id = (b - CB_HIST - CB_CONV) * 256 + t;   // 0..8191
        const int tIdx = id >> 11;
        const int rem = id & 2047;
        const int j = rem >> 4, cu = rem & 15;
        const float* W = (tIdx == 0) ? Wl1 : (tIdx == 1) ? Wr1 : (tIdx == 2) ? Wl2 : Wr2;
        const float4* p = (const float4*)(W + (size_t)j * DD + cu * 8);
        float4 v0 = p[0], v1 = p[1];
        __half2 h0 = __floats2half2_rn(v0.x, v0.y);
        __half2 h1 = __floats2half2_rn(v0.z, v0.w);
        __half2 h2 = __floats2half2_rn(v1.x, v1.y);
        __half2 h3 = __floats2half2_rn(v1.z, v1.w);
        __half* dst = wpack + (size_t)tIdx * 16384 + (size_t)j * DD + cu * 8;
        *(uint4*)dst = make_uint4(*(unsigned*)&h0, *(unsigned*)&h1,
                                  *(unsigned*)&h2, *(unsigned*)&h3);
    } else {
        // ---- global int64/int32 detection (for fill_kernel) ----
        __shared__ int nz;
        if (t == 0) nz = 0;
        __syncthreads();
        for (int i = t; i < 8192; i += 256)
            if (ebuf[2 * i + 1] != 0u) nz = 1;
        __syncthreads();
        if (t == 0) g_is64 = (nz == 0) ? 1 : 0;
    }
}

// ---------------------------------------------------------------------------
// scan1: per-1024-block exclusive scan of cnt, emits block sums
// ---------------------------------------------------------------------------
__global__ void scan1_kernel(const int* __restrict__ cnt, int* __restrict__ rp,
                             int* __restrict__ bs) {
    __shared__ int wsum[8];
    const int t = threadIdx.x, lane = t & 31, w = t >> 5;
    const int base = blockIdx.x * 1024 + t * 4;
    int v0 = (base + 0 < NN) ? cnt[base + 0] : 0;
    int v1 = (base + 1 < NN) ? cnt[base + 1] : 0;
    int v2 = (base + 2 < NN) ? cnt[base + 2] : 0;
    int v3 = (base + 3 < NN) ? cnt[base + 3] : 0;
    const int tot = v0 + v1 + v2 + v3;
    int inc = tot;
#pragma unroll
    for (int off = 1; off < 32; off <<= 1) {
        int n = __shfl_up_sync(0xffffffff, inc, off);
        if (lane >= off) inc += n;
    }
    if (lane == 31) wsum[w] = inc;
    __syncthreads();
    if (w == 0) {
        int s = (lane < 8) ? wsum[lane] : 0;
#pragma unroll
        for (int off = 1; off < 8; off <<= 1) {
            int n = __shfl_up_sync(0xffffffff, s, off);
            if (lane >= off) s += n;
        }
        if (lane < 8) wsum[lane] = s;
    }
    __syncthreads();
    const int wbase = (w > 0) ? wsum[w - 1] : 0;
    const int exc = wbase + inc - tot;
    if (base + 0 < NN) rp[base + 0] = exc;
    if (base + 1 < NN) rp[base + 1] = exc + v0;
    if (base + 2 < NN) rp[base + 2] = exc + v0 + v1;
    if (base + 3 < NN) rp[base + 3] = exc + v0 + v1 + v2;
    if (t == 255) bs[blockIdx.x] = wbase + inc;
}

// ---------------------------------------------------------------------------
// scan23: apply block-sum prefix; ALSO re-zero cnt for the next call.
// ---------------------------------------------------------------------------
__global__ void scan23_kernel(int* __restrict__ rp, int* __restrict__ pos,
                              const int* __restrict__ bs,
                              int* __restrict__ cnt) {
    __shared__ int sbs[NB_SCAN];
    const int t = threadIdx.x;
    if (t < NB_SCAN) sbs[t] = bs[t];
    __syncthreads();
    const int i = blockIdx.x * blockDim.x + t;
    if (i < NN) {
        const int k = i >> 10;
        int pre = 0;
        for (int j = 0; j < k; ++j) pre += sbs[j];
        const int v = rp[i] + pre;
        rp[i] = v;
        pos[i] = v;
        cnt[i] = 0;                    // maintain invariant for next call
    }
    if (i == 0) rp[NN] = NE;
}

// ---------------------------------------------------------------------------
// fill: 2 edges per thread via 16B loads
// ---------------------------------------------------------------------------
__global__ void fill_kernel(const void* __restrict__ edges, int* __restrict__ pos,
                            int* __restrict__ srcs) {
    const int is64 = g_is64;
    int i2 = blockIdx.x * blockDim.x + threadIdx.x;
    const int stride = gridDim.x * blockDim.x;
    if (is64) {
        const longlong2* sp = (const longlong2*)edges;
        const longlong2* dp = (const longlong2*)((const long long*)edges + NE);
        for (; i2 < NE / 2; i2 += stride) {
            longlong2 s = __ldg(&sp[i2]);
            longlong2 d = __ldg(&dp[i2]);
            srcs[atomicAdd(&pos[(int)d.x], 1)] = (int)s.x;
            srcs[atomicAdd(&pos[(int)d.y], 1)] = (int)s.y;
        }
    } else {
        const int2* sp = (const int2*)edges;
        const int2* dp = (const int2*)((const int*)edges + NE);
        for (; i2 < NE / 2; i2 += stride) {
            int2 s = __ldg(&sp[i2]);
            int2 d = __ldg(&dp[i2]);
            srcs[atomicAdd(&pos[d.x], 1)] = s.x;
            srcs[atomicAdd(&pos[d.y], 1)] = s.y;
        }
    }
}

// ---------------------------------------------------------------------------
// Gather: warp per dst node. Lane-parallel index fetch + shfl distribution.
// fp32 accumulate -> fp16 mean out.
// ---------------------------------------------------------------------------
__global__ void gather_f16_kernel(const __half* __restrict__ xin,
                                  const int* __restrict__ rp,
                                  const int* __restrict__ srcs,
                                  __half* __restrict__ aggf) {
    const int warp = (blockIdx.x * blockDim.x + threadIdx.x) >> 5;
    const int lane = threadIdx.x & 31;
    if (warp >= NN) return;
    const int s = rp[warp], e = rp[warp + 1];
    const int deg = e - s;
    float4 acc = make_float4(0.f, 0.f, 0.f, 0.f);

    const int myidx = (s + lane < e) ? srcs[s + lane] : 0;
    const int n = (deg < 32) ? deg : 32;

#pragma unroll 4
    for (int i = 0; i < n; ++i) {
        const int sidx = __shfl_sync(0xffffffff, myidx, i);
        const uint2 u = __ldg((const uint2*)(xin + (size_t)sidx * DD + lane * 4));
        float2 a0 = __half22float2(*(const __half2*)&u.x);
        float2 a1 = __half22float2(*(const __half2*)&u.y);
        acc.x += a0.x; acc.y += a0.y; acc.z += a1.x; acc.w += a1.y;
    }
    for (int i = s + 32; i < e; ++i) {
        const int sidx = srcs[i];
        const uint2 u = __ldg((const uint2*)(xin + (size_t)sidx * DD + lane * 4));
        float2 a0 = __half22float2(*(const __half2*)&u.x);
        float2 a1 = __half22float2(*(const __half2*)&u.y);
        acc.x += a0.x; acc.y += a0.y; acc.z += a1.x; acc.w += a1.y;
    }

    const float inv = 1.0f / fmaxf((float)deg, 1.0f);
    __half2 o0 = __floats2half2_rn(acc.x * inv, acc.y * inv);
    __half2 o1 = __floats2half2_rn(acc.z * inv, acc.w * inv);
    *(uint2*)(aggf + (size_t)warp * DD + lane * 4) =
        make_uint2(*(unsigned*)&o0, *(unsigned*)&o1);
}

// ---------------------------------------------------------------------------
// fp16 mma.sync node GEMM, cp.async double-buffered.
// out = [agg|x] @ [Wl;Wr]^T + bias ; 4 chunks of K=64 (single term).
// CTA: 128x128 C; 8 warps 2x4, each 64x32; SMEM rows padded to 144B.
// ---------------------------------------------------------------------------
#define PADB 144
#define ACH  (128 * PADB)          // 18432 bytes per buffer
#define NODE_SMEM (4 * ACH)        // 73728

__global__ void __launch_bounds__(256, 2)
node_mma_kernel(const __half* __restrict__ aggf,
                const __half* __restrict__ xf,    // x or h
                const __half* __restrict__ w,     // layer slots: +0 Wl, +16384 Wr
                const float* __restrict__ bias,
                float* __restrict__ outf,
                __half* __restrict__ of16,
                int relu_split)
{
    extern __shared__ char smem[];
    const uint32_t uS = smem_to_u32(smem);

    const int tid  = threadIdx.x;
    const int wid  = tid >> 5;
    const int lane = tid & 31;
    const int wm   = wid >> 2;          // 0..1
    const int wn   = wid & 3;           // 0..3
    const int row0 = blockIdx.x << 7;

    // 4 chunks: {agg,k0},{agg,k64},{x,k0},{x,k64} ; B: Wl/Wl/Wr/Wr
    const int aSrcT[4] = {0, 0, 1, 1};
    const int aKoT [4] = {0, 64, 0, 64};
    const int bSlT [4] = {0, 0, 1, 1};
    const int bKoT [4] = {0, 64, 0, 64};
    const __half* aBase[2] = {aggf, xf};

    const int a_row = wm * 64 + (lane & 15);
    const int a_kb  = ((lane >> 4) & 1) << 4;
    const int b_row = wn * 32 + (lane & 7);
    const int b_kb  = ((lane >> 3) & 1) << 4;

    float acc[4][4][4];
#pragma unroll
    for (int mt = 0; mt < 4; ++mt)
#pragma unroll
        for (int nt = 0; nt < 4; ++nt)
#pragma unroll
            for (int q = 0; q < 4; ++q) acc[mt][nt][q] = 0.f;

    // ---- issue chunk-0 loads ----
    {
        const __half* As = aBase[0] + (size_t)row0 * DD;
        const __half* Bs = w;
#pragma unroll
        for (int i = 0; i < 4; ++i) {
            const int u = i * 256 + tid;
            const int r = u >> 3, g = u & 7;
            cp_async16(uS + 0 * ACH + r * PADB + g * 16, As + (size_t)r * DD + g * 8);
        }
#pragma unroll
        for (int i = 0; i < 4; ++i) {
            const int u = i * 256 + tid;
            const int r = u >> 3, g = u & 7;
            cp_async16(uS + 2 * ACH + r * PADB + g * 16, Bs + (size_t)r * DD + g * 8);
        }
        CP_COMMIT();
    }

#pragma unroll
    for (int c = 0; c < 4; ++c) {
        __syncthreads();

        if (c < 3) {
            const int n = c + 1;
            const int nb = n & 1;
            {
                const __half* As = aBase[aSrcT[n]] + (size_t)row0 * DD + aKoT[n];
                const uint32_t dst = uS + nb * ACH;
#pragma unroll
                for (int i = 0; i < 4; ++i) {
                    const int u = i * 256 + tid;
                    const int r = u >> 3, g = u & 7;
                    cp_async16(dst + r * PADB + g * 16, As + (size_t)r * DD + g * 8);
                }
            }
            {
                const __half* Bs = w + (size_t)bSlT[n] * 16384 + bKoT[n];
                const uint32_t dst = uS + 2 * ACH + nb * ACH;
#pragma unroll
                for (int i = 0; i < 4; ++i) {
                    const int u = i * 256 + tid;
                    const int r = u >> 3, g = u & 7;
                    cp_async16(dst + r * PADB + g * 16, Bs + (size_t)r * DD + g * 8);
                }
            }
            CP_COMMIT();
            CP_WAIT1();
        } else {
            CP_WAIT0();
        }
        __syncthreads();

        const int cb = c & 1;
        const uint32_t uA = uS + cb * ACH;
        const uint32_t uB = uS + 2 * ACH + cb * ACH;

#pragma unroll
        for (int ks = 0; ks < 4; ++ks) {
            uint32_t af[4][4];
#pragma unroll
            for (int mt = 0; mt < 4; ++mt) {
                const uint32_t addr = uA + (a_row + mt * 16) * PADB + ks * 32 + a_kb;
                asm volatile("ldmatrix.sync.aligned.m8n8.x4.shared.b16 {%0,%1,%2,%3}, [%4];"
                             : "=r"(af[mt][0]), "=r"(af[mt][1]),
                               "=r"(af[mt][2]), "=r"(af[mt][3])
                             : "r"(addr));
            }
            uint32_t bfr[4][2];
#pragma unroll
            for (int nt = 0; nt < 4; ++nt) {
                const uint32_t addr = uB + (b_row + nt * 8) * PADB + ks * 32 + b_kb;
                asm volatile("ldmatrix.sync.aligned.m8n8.x2.shared.b16 {%0,%1}, [%2];"
                             : "=r"(bfr[nt][0]), "=r"(bfr[nt][1])
                             : "r"(addr));
            }
#pragma unroll
            for (int mt = 0; mt < 4; ++mt)
#pragma unroll
                for (int nt = 0; nt < 4; ++nt) {
                    asm volatile(
                        "mma.sync.aligned.m16n8k16.row.col.f32.f16.f16.f32 "
                        "{%0,%1,%2,%3}, {%4,%5,%6,%7}, {%8,%9}, {%0,%1,%2,%3};"
                        : "+f"(acc[mt][nt][0]), "+f"(acc[mt][nt][1]),
                          "+f"(acc[mt][nt][2]), "+f"(acc[mt][nt][3])
                        : "r"(af[mt][0]), "r"(af[mt][1]),
                          "r"(af[mt][2]), "r"(af[mt][3]),
                          "r"(bfr[nt][0]), "r"(bfr[nt][1]));
                }
        }
    }

    // ---- epilogue ----
    const int col_base = wn * 32 + ((lane & 3) << 1);
    float bv[4][2];
#pragma unroll
    for (int nt = 0; nt < 4; ++nt) {
        bv[nt][0] = __ldg(bias + col_base + nt * 8);
        bv[nt][1] = __ldg(bias + col_base + nt * 8 + 1);
    }

#pragma unroll
    for (int mt = 0; mt < 4; ++mt) {
        const int r0 = row0 + wm * 64 + mt * 16 + (lane >> 2);
        const int r1 = r0 + 8;
#pragma unroll
        for (int nt = 0; nt < 4; ++nt) {
            const int col = col_base + nt * 8;
            float v0 = acc[mt][nt][0] + bv[nt][0];
            float v1 = acc[mt][nt][1] + bv[nt][1];
            float v2 = acc[mt][nt][2] + bv[nt][0];
            float v3 = acc[mt][nt][3] + bv[nt][1];
            if (relu_split) {
                v0 = fmaxf(v0, 0.f); v1 = fmaxf(v1, 0.f);
                v2 = fmaxf(v2, 0.f); v3 = fmaxf(v3, 0.f);
                if (r0 < NN)
                    *(__half2*)(of16 + (size_t)r0 * DD + col) = __floats2half2_rn(v0, v1);
                if (r1 < NN)
                    *(__half2*)(of16 + (size_t)r1 * DD + col) = __floats2half2_rn(v2, v3);
            } else {
                if (r0 < NN) *(float2*)(outf + (size_t)r0 * DD + col) = make_float2(v0, v1);
                if (r1 < NN) *(float2*)(outf + (size_t)r1 * DD + col) = make_float2(v2, v3);
            }
        }
    }
}

// ---------------------------------------------------------------------------
// Launch sequence (default stream, graph-capturable, allocation-free)
// 8 kernels total.
// ---------------------------------------------------------------------------
extern "C" void kernel_launch(void* const* d_in, const int* in_sizes, int n_in,
                              void* d_out, int out_size)
{
    const float* x   = (const float*)d_in[0];
    const void*  ei  = d_in[1];
    const float* W1l = (const float*)d_in[2];
    const float* b1  = (const float*)d_in[3];
    const float* W1r = (const float*)d_in[4];
    const float* W2l = (const float*)d_in[5];
    const float* b2  = (const float*)d_in[6];
    const float* W2r = (const float*)d_in[7];
    float* out = (float*)d_out;

    __half *xf, *hf, *aggf, *wpack;
    int *srcs, *rp, *pos, *cnt, *bs;
    cudaGetSymbolAddress((void**)&xf,    g_xf);
    cudaGetSymbolAddress((void**)&hf,    g_hf);
    cudaGetSymbolAddress((void**)&aggf,  g_aggf);
    cudaGetSymbolAddress((void**)&wpack, g_wpack);
    cudaGetSymbolAddress((void**)&srcs,  g_srcs);
    cudaGetSymbolAddress((void**)&rp,    g_rp);
    cudaGetSymbolAddress((void**)&pos,   g_pos);
    cudaGetSymbolAddress((void**)&cnt,   g_cnt);
    cudaGetSymbolAddress((void**)&bs,    g_bs);

    cudaFuncSetAttribute(node_mma_kernel,
                         cudaFuncAttributeMaxDynamicSharedMemorySize, NODE_SMEM);

    // combo: hist | convert_x | prep_w | detect  (cnt==0 invariant on entry)
    combo_kernel<<<CB_TOTAL, 256>>>((const float4*)x, (const unsigned int*)ei,
                                    W1l, W1r, W2l, W2r, xf, wpack, cnt);

    // CSR build
    scan1_kernel<<<NB_SCAN, 256>>>(cnt, rp, bs);
    scan23_kernel<<<(NN + 255) / 256, 256>>>(rp, pos, bs, cnt);
    fill_kernel<<<1600, 256>>>(ei, pos, srcs);

    // Layer 1
    gather_f16_kernel<<<(NN * 32 + 255) / 256, 256>>>(xf, rp, srcs, aggf);
    node_mma_kernel<<<NTILE, 256, NODE_SMEM>>>(aggf, xf, wpack, b1,
                                               nullptr, hf, 1);

    // Layer 2
    gather_f16_kernel<<<(NN * 32 + 255) / 256, 256>>>(hf, rp, srcs, aggf);
    node_mma_kernel<<<NTILE, 256, NODE_SMEM>>>(aggf, hf, wpack + 2 * 16384, b2,
                                               out, nullptr, 0);
}